// round 5
// baseline (speedup 1.0000x reference)
#include <cuda_runtime.h>
#include <math.h>

#define NN 50000
#define NE 800000
#define FD 128
#define NG 128
#define NOUT 10

// ---------------- scratch (static device globals; allocation-free) ----------------
__device__ __align__(16) float g_h[(size_t)NN * FD];    // GEMM output / fc1 output (reused)
__device__ __align__(16) float g_a2[(size_t)NN * FD];   // layer-2 GEMM input (fused post-op of layer 1)
__device__ float g_inv_out[NN];
__device__ float g_inv_in[NN];
__device__ int   g_cnt[2 * NN];    // [0..NN) out-degree (src), [NN..2NN) in-degree (dst)
__device__ int   g_row[NN + 1];    // CSR row offsets (by dst)
__device__ int   g_cur[NN];        // fill cursors
__device__ int   g_csr[NE];        // src node id per in-edge, grouped by dst
__device__ float g_bn[2 * FD];     // BN scale / shift

// ---------------- zero / degree / inverse-sqrt ----------------
__global__ void k_zero_cnt() {
    int i = blockIdx.x * blockDim.x + threadIdx.x;
    if (i < 2 * NN) g_cnt[i] = 0;
}

__global__ void k_zero_out(float* __restrict__ o) {
    int i = blockIdx.x * blockDim.x + threadIdx.x;
    if (i < NG * FD) o[i] = 0.f;
}

__global__ void k_deg(const int* __restrict__ src, const int* __restrict__ dst) {
    int e = blockIdx.x * blockDim.x + threadIdx.x;
    if (e < NE) {
        atomicAdd(&g_cnt[src[e]], 1);
        atomicAdd(&g_cnt[NN + dst[e]], 1);
    }
}

__global__ void k_inv() {
    int i = blockIdx.x * blockDim.x + threadIdx.x;
    if (i < NN) {
        int a = g_cnt[i];      if (a < 1) a = 1;
        int b = g_cnt[NN + i]; if (b < 1) b = 1;
        g_inv_out[i] = rsqrtf((float)a);
        g_inv_in[i]  = rsqrtf((float)b);
    }
}

// ---------------- single-block exclusive scan over in-degrees -> CSR row offsets ----------------
__global__ void __launch_bounds__(1024) k_scan() {
    __shared__ int wsum[32];
    const int CH = 49;                 // 1024*49 = 50176 >= NN
    int t = threadIdx.x;
    int base = t * CH;
    int s = 0;
    for (int j = 0; j < CH; j++) {
        int idx = base + j;
        if (idx < NN) s += g_cnt[NN + idx];
    }
    int lane = t & 31, wid = t >> 5;
    int inc = s;
#pragma unroll
    for (int off = 1; off < 32; off <<= 1) {
        int v = __shfl_up_sync(0xffffffffu, inc, off);
        if (lane >= off) inc += v;
    }
    if (lane == 31) wsum[wid] = inc;
    __syncthreads();
    if (wid == 0) {
        int v = wsum[lane];
#pragma unroll
        for (int off = 1; off < 32; off <<= 1) {
            int u = __shfl_up_sync(0xffffffffu, v, off);
            if (lane >= off) v += u;
        }
        wsum[lane] = v;
    }
    __syncthreads();
    int excl = inc - s + (wid > 0 ? wsum[wid - 1] : 0);
    int run = excl;
    for (int j = 0; j < CH; j++) {
        int idx = base + j;
        if (idx < NN) {
            g_row[idx] = run;
            g_cur[idx] = run;
            run += g_cnt[NN + idx];
        }
    }
    // thread 1023's range is entirely >= NN, so its s==0 and excl == total
    if (t == 1023) g_row[NN] = excl;
}

__global__ void k_fill(const int* __restrict__ src, const int* __restrict__ dst) {
    int e = blockIdx.x * blockDim.x + threadIdx.x;
    if (e < NE) {
        int pos = atomicAdd(&g_cur[dst[e]], 1);
        g_csr[pos] = src[e];
    }
}

// ---------------- fp32 GEMM: [NN,128] @ [128,128] -> g_h ----------------
// LAYER 1: A = n_feat scaled by inv_sqrt_out per row.   LAYER 2: A = g_a2 (pre-fused).
template <int LAYER>
__global__ void __launch_bounds__(256) k_gemm(const float* __restrict__ Ain,
                                              const float* __restrict__ W) {
    extern __shared__ float sm[];
    float* As = sm;               // transposed tile: As[k*132 + m], 128x(128 pad 132)
    float* Ws = sm + FD * 132;    // Ws[k*128 + n]

    const float* Aptr = (LAYER == 1) ? Ain : (const float*)g_a2;
    int tid = threadIdx.x;
    int m0 = blockIdx.x * 128;

    const float4* W4 = (const float4*)W;
    float4* Ws4 = (float4*)Ws;
#pragma unroll
    for (int it = 0; it < 16; it++) Ws4[tid + it * 256] = W4[tid + it * 256];

#pragma unroll
    for (int it = 0; it < 16; it++) {
        int idx = tid + it * 256;          // 0..4095
        int mm = idx >> 5;
        int kk4 = idx & 31;
        int m = m0 + mm;
        float4 v = make_float4(0.f, 0.f, 0.f, 0.f);
        if (m < NN) {
            v = *(const float4*)(Aptr + (size_t)m * FD + kk4 * 4);
            if (LAYER == 1) {
                float s = g_inv_out[m];
                v.x *= s; v.y *= s; v.z *= s; v.w *= s;
            }
        }
        As[(kk4 * 4 + 0) * 132 + mm] = v.x;
        As[(kk4 * 4 + 1) * 132 + mm] = v.y;
        As[(kk4 * 4 + 2) * 132 + mm] = v.z;
        As[(kk4 * 4 + 3) * 132 + mm] = v.w;
    }
    __syncthreads();

    int tx = tid & 15, ty = tid >> 4;
    float acc[8][8];
#pragma unroll
    for (int i = 0; i < 8; i++)
#pragma unroll
        for (int j = 0; j < 8; j++) acc[i][j] = 0.f;

    const float* Ap = As + ty * 8;
    const float* Wp = Ws + tx * 8;
#pragma unroll 8
    for (int k = 0; k < 128; k++) {
        float4 a0 = *(const float4*)(Ap + k * 132);
        float4 a1 = *(const float4*)(Ap + k * 132 + 4);
        float4 b0 = *(const float4*)(Wp + k * 128);
        float4 b1 = *(const float4*)(Wp + k * 128 + 4);
        float a[8] = {a0.x, a0.y, a0.z, a0.w, a1.x, a1.y, a1.z, a1.w};
        float b[8] = {b0.x, b0.y, b0.z, b0.w, b1.x, b1.y, b1.z, b1.w};
#pragma unroll
        for (int i = 0; i < 8; i++)
#pragma unroll
            for (int j = 0; j < 8; j++) acc[i][j] = fmaf(a[i], b[j], acc[i][j]);
    }

#pragma unroll
    for (int i = 0; i < 8; i++) {
        int m = m0 + ty * 8 + i;
        if (m < NN) {
            float4 o0 = make_float4(acc[i][0], acc[i][1], acc[i][2], acc[i][3]);
            float4 o1 = make_float4(acc[i][4], acc[i][5], acc[i][6], acc[i][7]);
            *(float4*)(g_h + (size_t)m * FD + tx * 8) = o0;
            *(float4*)(g_h + (size_t)m * FD + tx * 8 + 4) = o1;
        }
    }
}

// ---------------- CSR gather (warp per node) ----------------
// LAYER 1: g_a2[n] = relu(sum * inv_in + b1) * inv_out
// LAYER 2: x2 = relu(sum * inv_in + b2); block-pre-reduced sum-pool into emb[graph_ids[n]]
template <int LAYER>
__global__ void __launch_bounds__(256) k_gather(const float* __restrict__ bias,
                                                const int* __restrict__ gids,
                                                float* __restrict__ emb) {
    __shared__ float s_x[8 * FD];
    __shared__ int s_g[8];
    int n = (blockIdx.x * blockDim.x + threadIdx.x) >> 5;
    int lane = threadIdx.x & 31;
    int wid = threadIdx.x >> 5;

    float4 acc = make_float4(0.f, 0.f, 0.f, 0.f);
    if (n < NN) {
        int r0 = g_row[n], r1 = g_row[n + 1];
        const float* hb = g_h + (size_t)lane * 4;
        int i = r0;
        for (; i + 4 <= r1; i += 4) {
            int s0 = g_csr[i + 0], s1 = g_csr[i + 1], s2 = g_csr[i + 2], s3 = g_csr[i + 3];
            float4 v0 = *(const float4*)(hb + (size_t)s0 * FD);
            float4 v1 = *(const float4*)(hb + (size_t)s1 * FD);
            float4 v2 = *(const float4*)(hb + (size_t)s2 * FD);
            float4 v3 = *(const float4*)(hb + (size_t)s3 * FD);
            acc.x += (v0.x + v1.x) + (v2.x + v3.x);
            acc.y += (v0.y + v1.y) + (v2.y + v3.y);
            acc.z += (v0.z + v1.z) + (v2.z + v3.z);
            acc.w += (v0.w + v1.w) + (v2.w + v3.w);
        }
        for (; i < r1; i++) {
            int s0 = g_csr[i];
            float4 v0 = *(const float4*)(hb + (size_t)s0 * FD);
            acc.x += v0.x; acc.y += v0.y; acc.z += v0.z; acc.w += v0.w;
        }
        float ii = g_inv_in[n];
        float4 b = *(const float4*)(bias + lane * 4);
        acc.x = fmaxf(fmaf(acc.x, ii, b.x), 0.f);
        acc.y = fmaxf(fmaf(acc.y, ii, b.y), 0.f);
        acc.z = fmaxf(fmaf(acc.z, ii, b.z), 0.f);
        acc.w = fmaxf(fmaf(acc.w, ii, b.w), 0.f);
        if (LAYER == 1) {
            float io = g_inv_out[n];
            acc.x *= io; acc.y *= io; acc.z *= io; acc.w *= io;
            *(float4*)(g_a2 + (size_t)n * FD + lane * 4) = acc;
        }
    }

    if (LAYER == 2) {
        *(float4*)(s_x + wid * FD + lane * 4) = acc;
        if (lane == 0) s_g[wid] = (n < NN) ? gids[n] : -1;
        __syncthreads();
        int t = threadIdx.x;
        if (t < FD) {
            int prev = -1;
            float run = 0.f;
#pragma unroll
            for (int w = 0; w < 8; w++) {
                int g = s_g[w];
                if (g < 0) continue;
                if (g != prev) {
                    if (prev >= 0) atomicAdd(&emb[prev * FD + t], run);
                    prev = g;
                    run = 0.f;
                }
                run += s_x[w * FD + t];
            }
            if (prev >= 0) atomicAdd(&emb[prev * FD + t], run);
        }
    }
}

// ---------------- BatchNorm stats (training-mode batch stats, biased var) ----------------
__global__ void k_bn(const float* __restrict__ emb, const float* __restrict__ gamma,
                     const float* __restrict__ beta) {
    int j = threadIdx.x;  // 128 threads, one per feature
    float mu = 0.f;
    for (int b = 0; b < NG; b++) mu += emb[b * FD + j];
    mu *= (1.f / NG);
    float var = 0.f;
    for (int b = 0; b < NG; b++) {
        float d = emb[b * FD + j] - mu;
        var += d * d;
    }
    var *= (1.f / NG);
    float sc = gamma[j] * rsqrtf(var + 1e-5f);
    g_bn[j] = sc;
    g_bn[FD + j] = beta[j] - mu * sc;
}

// ---------------- fc1: relu( BN(emb) @ fc1_w + fc1_b ) -> g_h[0:128*128] ----------------
__global__ void __launch_bounds__(256) k_fc1(const float* __restrict__ emb,
                                             const float* __restrict__ w,
                                             const float* __restrict__ fb) {
    extern __shared__ float sm[];
    float* sw = sm;            // 128x128
    float* sa = sm + FD * FD;  // 8x128 (BN-normalized rows)
    int tid = threadIdx.x;
    int b0 = blockIdx.x * 8;

    const float4* w4 = (const float4*)w;
#pragma unroll
    for (int it = 0; it < 16; it++) ((float4*)sw)[tid + it * 256] = w4[tid + it * 256];
#pragma unroll
    for (int it = 0; it < 4; it++) {
        int idx = tid + it * 256;  // 0..1023
        int r = idx >> 7, k = idx & 127;
        sa[idx] = emb[(b0 + r) * FD + k] * g_bn[k] + g_bn[FD + k];
    }
    __syncthreads();

    int j = tid & 127;
    int rr = tid >> 7;  // 0 or 1
    float bias = fb[j];
    float acc[4] = {bias, bias, bias, bias};
#pragma unroll 8
    for (int k = 0; k < 128; k++) {
        float wv = sw[k * FD + j];
#pragma unroll
        for (int q = 0; q < 4; q++) acc[q] = fmaf(sa[(rr + q * 2) * FD + k], wv, acc[q]);
    }
#pragma unroll
    for (int q = 0; q < 4; q++) {
        int b = b0 + rr + q * 2;
        g_h[(size_t)b * FD + j] = fmaxf(acc[q], 0.f);
    }
}

// ---------------- fc2 + log_softmax ----------------
__global__ void __launch_bounds__(1024) k_fc2ls(const float* __restrict__ w2,
                                                const float* __restrict__ b2o,
                                                float* __restrict__ outp) {
    __shared__ float slog[NG * NOUT];
    int tid = threadIdx.x;
    for (int l = tid; l < NG * NOUT; l += 1024) {
        int b = l / NOUT, o = l % NOUT;
        float acc = b2o[o];
        const float* hrow = g_h + (size_t)b * FD;
#pragma unroll 8
        for (int k = 0; k < 128; k++) acc = fmaf(hrow[k], w2[k * NOUT + o], acc);
        slog[l] = acc;
    }
    __syncthreads();
    if (tid < NG) {
        float m = -1e30f;
#pragma unroll
        for (int o = 0; o < NOUT; o++) m = fmaxf(m, slog[tid * NOUT + o]);
        float s = 0.f;
#pragma unroll
        for (int o = 0; o < NOUT; o++) s += expf(slog[tid * NOUT + o] - m);
        float lse = m + logf(s);
#pragma unroll
        for (int o = 0; o < NOUT; o++) outp[tid * NOUT + o] = slog[tid * NOUT + o] - lse;
    }
}

// ---------------- launch ----------------
extern "C" void kernel_launch(void* const* d_in, const int* in_sizes, int n_in,
                              void* d_out, int out_size) {
    (void)in_sizes; (void)n_in; (void)out_size;
    const float* n_feat = (const float*)d_in[0];
    const int*   src    = (const int*)d_in[1];
    const int*   dst    = (const int*)d_in[2];
    const int*   gids   = (const int*)d_in[3];
    const float* W1     = (const float*)d_in[4];
    const float* b1     = (const float*)d_in[5];
    const float* W2     = (const float*)d_in[6];
    const float* b2     = (const float*)d_in[7];
    const float* gamma  = (const float*)d_in[8];
    const float* beta   = (const float*)d_in[9];
    const float* fc1w   = (const float*)d_in[10];
    const float* fc1b   = (const float*)d_in[11];
    const float* fc2w   = (const float*)d_in[12];
    const float* fc2b   = (const float*)d_in[13];
    float* out = (float*)d_out;  // [0:16384) embedding, [16384:17664) log_softmax

    const int smem_gemm = (FD * 132 + FD * FD) * (int)sizeof(float);   // 133,120 B
    const int smem_fc1  = (FD * FD + 8 * FD) * (int)sizeof(float);     //  69,632 B
    cudaFuncSetAttribute(k_gemm<1>, cudaFuncAttributeMaxDynamicSharedMemorySize, smem_gemm);
    cudaFuncSetAttribute(k_gemm<2>, cudaFuncAttributeMaxDynamicSharedMemorySize, smem_gemm);
    cudaFuncSetAttribute(k_fc1,     cudaFuncAttributeMaxDynamicSharedMemorySize, smem_fc1);

    k_zero_cnt<<<(2 * NN + 255) / 256, 256>>>();
    k_deg<<<(NE + 255) / 256, 256>>>(src, dst);
    k_inv<<<(NN + 255) / 256, 256>>>();
    k_scan<<<1, 1024>>>();
    k_fill<<<(NE + 255) / 256, 256>>>(src, dst);

    // layer 1
    k_gemm<1><<<(NN + 127) / 128, 256, smem_gemm>>>(n_feat, W1);
    k_gather<1><<<(NN * 32 + 255) / 256, 256>>>(b1, (const int*)nullptr, (float*)nullptr);

    // layer 2 (+ fused sum-pool into d_out embedding)
    k_gemm<2><<<(NN + 127) / 128, 256, smem_gemm>>>((const float*)nullptr, W2);
    k_zero_out<<<(NG * FD + 255) / 256, 256>>>(out);
    k_gather<2><<<(NN * 32 + 255) / 256, 256>>>(b2, gids, out);

    // head
    k_bn<<<1, 128>>>(out, gamma, beta);
    k_fc1<<<NG / 8, 256, smem_fc1>>>(out, fc1w, fc1b);
    k_fc2ls<<<1, 1024>>>(fc2w, fc2b, out + NG * FD);
}

// round 7
// speedup vs baseline: 1.3151x; 1.3151x over previous
#include <cuda_runtime.h>
#include <math.h>

#define NN 50000
#define NE 800000
#define FD 128
#define NG 128
#define NOUT 10
#define NB ((NN + 1023) / 1024)   // 49 scan blocks

// ---------------- scratch (static device globals; allocation-free) ----------------
__device__ __align__(16) float g_h[(size_t)NN * FD];    // GEMM output / fc1 output (reused)
__device__ __align__(16) float g_a2[(size_t)NN * FD];   // layer-2 GEMM input (fused post-op of layer 1)
__device__ float g_inv_out[NN];
__device__ float g_inv_in[NN];
__device__ int   g_cnt[2 * NN];    // [0..NN) out-degree (src), [NN..2NN) in-degree (dst)
__device__ int   g_row[NN + 1];    // CSR row offsets (by dst)
__device__ int   g_cur[NN];        // fill cursors
__device__ int   g_csr[NE];        // src node id per in-edge, grouped by dst
__device__ float g_bn[2 * FD];     // BN scale / shift
__device__ int   g_bsum[64];       // per-block in-degree sums
__device__ int   g_boff[64];       // exclusive block offsets

// ---------------- zero / degree / inverse-sqrt ----------------
__global__ void k_zero_cnt() {
    int i = blockIdx.x * blockDim.x + threadIdx.x;
    if (i < 2 * NN) g_cnt[i] = 0;
}

__global__ void k_zero_out(float* __restrict__ o) {
    int i = blockIdx.x * blockDim.x + threadIdx.x;
    if (i < NG * FD) o[i] = 0.f;
}

__global__ void k_deg(const int* __restrict__ src, const int* __restrict__ dst) {
    int e = blockIdx.x * blockDim.x + threadIdx.x;
    if (e < NE) {
        atomicAdd(&g_cnt[src[e]], 1);
        atomicAdd(&g_cnt[NN + dst[e]], 1);
    }
}

__global__ void k_inv() {
    int i = blockIdx.x * blockDim.x + threadIdx.x;
    if (i < NN) {
        int a = g_cnt[i];      if (a < 1) a = 1;
        int b = g_cnt[NN + i]; if (b < 1) b = 1;
        g_inv_out[i] = rsqrtf((float)a);
        g_inv_in[i]  = rsqrtf((float)b);
    }
}

// ---------------- multi-block exclusive scan over in-degrees -> CSR row offsets ----------------
// Phase 1: per-block sums (NB blocks x 1024 elements, 256 threads x 4)
__global__ void __launch_bounds__(256) k_bsum() {
    __shared__ int wsum[8];
    int b = blockIdx.x, t = threadIdx.x;
    int idx = b * 1024 + t * 4;
    int s = 0;
#pragma unroll
    for (int j = 0; j < 4; j++)
        if (idx + j < NN) s += g_cnt[NN + idx + j];
    int lane = t & 31, w = t >> 5;
#pragma unroll
    for (int off = 16; off > 0; off >>= 1) s += __shfl_down_sync(0xffffffffu, s, off);
    if (lane == 0) wsum[w] = s;
    __syncthreads();
    if (t == 0) {
        int tot = 0;
#pragma unroll
        for (int i = 0; i < 8; i++) tot += wsum[i];
        g_bsum[b] = tot;
    }
}

// Phase 2: one warp scans NB (<=64) block sums; also writes g_row[NN] = total
__global__ void k_scan_bsums() {
    int lane = threadIdx.x;  // 32 threads
    int a0 = (lane < NB) ? g_bsum[lane] : 0;
    int a1 = (32 + lane < NB) ? g_bsum[32 + lane] : 0;
    int i0 = a0, i1 = a1;
#pragma unroll
    for (int off = 1; off < 32; off <<= 1) {
        int v = __shfl_up_sync(0xffffffffu, i0, off);
        if (lane >= off) i0 += v;
        int u = __shfl_up_sync(0xffffffffu, i1, off);
        if (lane >= off) i1 += u;
    }
    int tot0 = __shfl_sync(0xffffffffu, i0, 31);
    g_boff[lane] = i0 - a0;
    if (32 + lane < 64) g_boff[32 + lane] = tot0 + i1 - a1;
    if (lane == 31) g_row[NN] = tot0 + i1;
}

// Phase 3: per-block local exclusive scan + block offset -> g_row / g_cur
__global__ void __launch_bounds__(256) k_rows() {
    __shared__ int wsum[8];
    int b = blockIdx.x, t = threadIdx.x;
    int idx = b * 1024 + t * 4;
    int c[4];
    int s = 0;
#pragma unroll
    for (int j = 0; j < 4; j++) {
        c[j] = (idx + j < NN) ? g_cnt[NN + idx + j] : 0;
        s += c[j];
    }
    int lane = t & 31, w = t >> 5;
    int inc = s;
#pragma unroll
    for (int off = 1; off < 32; off <<= 1) {
        int v = __shfl_up_sync(0xffffffffu, inc, off);
        if (lane >= off) inc += v;
    }
    if (lane == 31) wsum[w] = inc;
    __syncthreads();
    if (w == 0 && lane < 8) {
        int v = wsum[lane];
#pragma unroll
        for (int off = 1; off < 8; off <<= 1) {
            int u = __shfl_up_sync(0xffu, v, off);
            if (lane >= off) v += u;
        }
        wsum[lane] = v;
    }
    __syncthreads();
    int run = inc - s + (w > 0 ? wsum[w - 1] : 0) + g_boff[b];
#pragma unroll
    for (int j = 0; j < 4; j++) {
        if (idx + j < NN) {
            g_row[idx + j] = run;
            g_cur[idx + j] = run;
            run += c[j];
        }
    }
}

__global__ void k_fill(const int* __restrict__ src, const int* __restrict__ dst) {
    int e = blockIdx.x * blockDim.x + threadIdx.x;
    if (e < NE) {
        int pos = atomicAdd(&g_cur[dst[e]], 1);
        g_csr[pos] = src[e];
    }
}

// ---------------- fp32 GEMM: [NN,128] @ [128,128] -> g_h ----------------
// LAYER 1: A = n_feat scaled by inv_sqrt_out per row.   LAYER 2: A = g_a2 (pre-fused).
template <int LAYER>
__global__ void __launch_bounds__(256) k_gemm(const float* __restrict__ Ain,
                                              const float* __restrict__ W) {
    extern __shared__ float sm[];
    float* As = sm;               // transposed tile: As[k*132 + m], 128x(128 pad 132)
    float* Ws = sm + FD * 132;    // Ws[k*128 + n]

    const float* Aptr = (LAYER == 1) ? Ain : (const float*)g_a2;
    int tid = threadIdx.x;
    int m0 = blockIdx.x * 128;

    const float4* W4 = (const float4*)W;
    float4* Ws4 = (float4*)Ws;
#pragma unroll
    for (int it = 0; it < 16; it++) Ws4[tid + it * 256] = W4[tid + it * 256];

#pragma unroll
    for (int it = 0; it < 16; it++) {
        int idx = tid + it * 256;          // 0..4095
        int mm = idx >> 5;
        int kk4 = idx & 31;
        int m = m0 + mm;
        float4 v = make_float4(0.f, 0.f, 0.f, 0.f);
        if (m < NN) {
            v = *(const float4*)(Aptr + (size_t)m * FD + kk4 * 4);
            if (LAYER == 1) {
                float s = g_inv_out[m];
                v.x *= s; v.y *= s; v.z *= s; v.w *= s;
            }
        }
        As[(kk4 * 4 + 0) * 132 + mm] = v.x;
        As[(kk4 * 4 + 1) * 132 + mm] = v.y;
        As[(kk4 * 4 + 2) * 132 + mm] = v.z;
        As[(kk4 * 4 + 3) * 132 + mm] = v.w;
    }
    __syncthreads();

    int tx = tid & 15, ty = tid >> 4;
    float acc[8][8];
#pragma unroll
    for (int i = 0; i < 8; i++)
#pragma unroll
        for (int j = 0; j < 8; j++) acc[i][j] = 0.f;

    const float* Ap = As + ty * 8;
    const float* Wp = Ws + tx * 8;
#pragma unroll 8
    for (int k = 0; k < 128; k++) {
        float4 a0 = *(const float4*)(Ap + k * 132);
        float4 a1 = *(const float4*)(Ap + k * 132 + 4);
        float4 b0 = *(const float4*)(Wp + k * 128);
        float4 b1 = *(const float4*)(Wp + k * 128 + 4);
        float a[8] = {a0.x, a0.y, a0.z, a0.w, a1.x, a1.y, a1.z, a1.w};
        float b[8] = {b0.x, b0.y, b0.z, b0.w, b1.x, b1.y, b1.z, b1.w};
#pragma unroll
        for (int i = 0; i < 8; i++)
#pragma unroll
            for (int j = 0; j < 8; j++) acc[i][j] = fmaf(a[i], b[j], acc[i][j]);
    }

#pragma unroll
    for (int i = 0; i < 8; i++) {
        int m = m0 + ty * 8 + i;
        if (m < NN) {
            float4 o0 = make_float4(acc[i][0], acc[i][1], acc[i][2], acc[i][3]);
            float4 o1 = make_float4(acc[i][4], acc[i][5], acc[i][6], acc[i][7]);
            *(float4*)(g_h + (size_t)m * FD + tx * 8) = o0;
            *(float4*)(g_h + (size_t)m * FD + tx * 8 + 4) = o1;
        }
    }
}

// ---------------- CSR gather (warp per node) ----------------
// LAYER 1: g_a2[n] = relu(sum * inv_in + b1) * inv_out
// LAYER 2: x2 = relu(sum * inv_in + b2); block-pre-reduced sum-pool into emb[graph_ids[n]]
template <int LAYER>
__global__ void __launch_bounds__(256) k_gather(const float* __restrict__ bias,
                                                const int* __restrict__ gids,
                                                float* __restrict__ emb) {
    __shared__ float s_x[8 * FD];
    __shared__ int s_g[8];
    int n = (blockIdx.x * blockDim.x + threadIdx.x) >> 5;
    int lane = threadIdx.x & 31;
    int wid = threadIdx.x >> 5;

    float4 acc = make_float4(0.f, 0.f, 0.f, 0.f);
    if (n < NN) {
        int r0 = g_row[n], r1 = g_row[n + 1];
        const float* hb = g_h + (size_t)lane * 4;
        int i = r0;
        for (; i + 4 <= r1; i += 4) {
            int s0 = g_csr[i + 0], s1 = g_csr[i + 1], s2 = g_csr[i + 2], s3 = g_csr[i + 3];
            float4 v0 = *(const float4*)(hb + (size_t)s0 * FD);
            float4 v1 = *(const float4*)(hb + (size_t)s1 * FD);
            float4 v2 = *(const float4*)(hb + (size_t)s2 * FD);
            float4 v3 = *(const float4*)(hb + (size_t)s3 * FD);
            acc.x += (v0.x + v1.x) + (v2.x + v3.x);
            acc.y += (v0.y + v1.y) + (v2.y + v3.y);
            acc.z += (v0.z + v1.z) + (v2.z + v3.z);
            acc.w += (v0.w + v1.w) + (v2.w + v3.w);
        }
        for (; i < r1; i++) {
            int s0 = g_csr[i];
            float4 v0 = *(const float4*)(hb + (size_t)s0 * FD);
            acc.x += v0.x; acc.y += v0.y; acc.z += v0.z; acc.w += v0.w;
        }
        float ii = g_inv_in[n];
        float4 b = *(const float4*)(bias + lane * 4);
        acc.x = fmaxf(fmaf(acc.x, ii, b.x), 0.f);
        acc.y = fmaxf(fmaf(acc.y, ii, b.y), 0.f);
        acc.z = fmaxf(fmaf(acc.z, ii, b.z), 0.f);
        acc.w = fmaxf(fmaf(acc.w, ii, b.w), 0.f);
        if (LAYER == 1) {
            float io = g_inv_out[n];
            acc.x *= io; acc.y *= io; acc.z *= io; acc.w *= io;
            *(float4*)(g_a2 + (size_t)n * FD + lane * 4) = acc;
        }
    }

    if (LAYER == 2) {
        *(float4*)(s_x + wid * FD + lane * 4) = acc;
        if (lane == 0) s_g[wid] = (n < NN) ? gids[n] : -1;
        __syncthreads();
        int t = threadIdx.x;
        if (t < FD) {
            int prev = -1;
            float run = 0.f;
#pragma unroll
            for (int w = 0; w < 8; w++) {
                int g = s_g[w];
                if (g < 0) continue;
                if (g != prev) {
                    if (prev >= 0) atomicAdd(&emb[prev * FD + t], run);
                    prev = g;
                    run = 0.f;
                }
                run += s_x[w * FD + t];
            }
            if (prev >= 0) atomicAdd(&emb[prev * FD + t], run);
        }
    }
}

// ---------------- BatchNorm stats (training-mode batch stats, biased var) ----------------
__global__ void k_bn(const float* __restrict__ emb, const float* __restrict__ gamma,
                     const float* __restrict__ beta) {
    int j = threadIdx.x;  // 128 threads, one per feature
    float mu = 0.f;
    for (int b = 0; b < NG; b++) mu += emb[b * FD + j];
    mu *= (1.f / NG);
    float var = 0.f;
    for (int b = 0; b < NG; b++) {
        float d = emb[b * FD + j] - mu;
        var += d * d;
    }
    var *= (1.f / NG);
    float sc = gamma[j] * rsqrtf(var + 1e-5f);
    g_bn[j] = sc;
    g_bn[FD + j] = beta[j] - mu * sc;
}

// ---------------- fc1: relu( BN(emb) @ fc1_w + fc1_b ) -> g_h[0:128*128] ----------------
__global__ void __launch_bounds__(256) k_fc1(const float* __restrict__ emb,
                                             const float* __restrict__ w,
                                             const float* __restrict__ fb) {
    extern __shared__ float sm[];
    float* sw = sm;            // 128x128
    float* sa = sm + FD * FD;  // 8x128 (BN-normalized rows)
    int tid = threadIdx.x;
    int b0 = blockIdx.x * 8;

    const float4* w4 = (const float4*)w;
#pragma unroll
    for (int it = 0; it < 16; it++) ((float4*)sw)[tid + it * 256] = w4[tid + it * 256];
#pragma unroll
    for (int it = 0; it < 4; it++) {
        int idx = tid + it * 256;  // 0..1023
        int r = idx >> 7, k = idx & 127;
        sa[idx] = emb[(b0 + r) * FD + k] * g_bn[k] + g_bn[FD + k];
    }
    __syncthreads();

    int j = tid & 127;
    int rr = tid >> 7;  // 0 or 1
    float bias = fb[j];
    float acc[4] = {bias, bias, bias, bias};
#pragma unroll 8
    for (int k = 0; k < 128; k++) {
        float wv = sw[k * FD + j];
#pragma unroll
        for (int q = 0; q < 4; q++) acc[q] = fmaf(sa[(rr + q * 2) * FD + k], wv, acc[q]);
    }
#pragma unroll
    for (int q = 0; q < 4; q++) {
        int b = b0 + rr + q * 2;
        g_h[(size_t)b * FD + j] = fmaxf(acc[q], 0.f);
    }
}

// ---------------- fc2 + log_softmax ----------------
__global__ void __launch_bounds__(1024) k_fc2ls(const float* __restrict__ w2,
                                                const float* __restrict__ b2o,
                                                float* __restrict__ outp) {
    __shared__ float slog[NG * NOUT];
    int tid = threadIdx.x;
    for (int l = tid; l < NG * NOUT; l += 1024) {
        int b = l / NOUT, o = l % NOUT;
        float acc = b2o[o];
        const float* hrow = g_h + (size_t)b * FD;
#pragma unroll 8
        for (int k = 0; k < 128; k++) acc = fmaf(hrow[k], w2[k * NOUT + o], acc);
        slog[l] = acc;
    }
    __syncthreads();
    if (tid < NG) {
        float m = -1e30f;
#pragma unroll
        for (int o = 0; o < NOUT; o++) m = fmaxf(m, slog[tid * NOUT + o]);
        float s = 0.f;
#pragma unroll
        for (int o = 0; o < NOUT; o++) s += expf(slog[tid * NOUT + o] - m);
        float lse = m + logf(s);
#pragma unroll
        for (int o = 0; o < NOUT; o++) outp[tid * NOUT + o] = slog[tid * NOUT + o] - lse;
    }
}

// ---------------- launch ----------------
extern "C" void kernel_launch(void* const* d_in, const int* in_sizes, int n_in,
                              void* d_out, int out_size) {
    (void)in_sizes; (void)n_in; (void)out_size;
    const float* n_feat = (const float*)d_in[0];
    const int*   src    = (const int*)d_in[1];
    const int*   dst    = (const int*)d_in[2];
    const int*   gids   = (const int*)d_in[3];
    const float* W1     = (const float*)d_in[4];
    const float* b1     = (const float*)d_in[5];
    const float* W2     = (const float*)d_in[6];
    const float* b2     = (const float*)d_in[7];
    const float* gamma  = (const float*)d_in[8];
    const float* beta   = (const float*)d_in[9];
    const float* fc1w   = (const float*)d_in[10];
    const float* fc1b   = (const float*)d_in[11];
    const float* fc2w   = (const float*)d_in[12];
    const float* fc2b   = (const float*)d_in[13];
    float* out = (float*)d_out;  // [0:16384) embedding, [16384:17664) log_softmax

    const int smem_gemm = (FD * 132 + FD * FD) * (int)sizeof(float);   // 133,120 B
    const int smem_fc1  = (FD * FD + 8 * FD) * (int)sizeof(float);     //  69,632 B
    cudaFuncSetAttribute(k_gemm<1>, cudaFuncAttributeMaxDynamicSharedMemorySize, smem_gemm);
    cudaFuncSetAttribute(k_gemm<2>, cudaFuncAttributeMaxDynamicSharedMemorySize, smem_gemm);
    cudaFuncSetAttribute(k_fc1,     cudaFuncAttributeMaxDynamicSharedMemorySize, smem_fc1);

    k_zero_cnt<<<(2 * NN + 255) / 256, 256>>>();
    k_deg<<<(NE + 255) / 256, 256>>>(src, dst);
    k_inv<<<(NN + 255) / 256, 256>>>();
    k_bsum<<<NB, 256>>>();
    k_scan_bsums<<<1, 32>>>();
    k_rows<<<NB, 256>>>();
    k_fill<<<(NE + 255) / 256, 256>>>(src, dst);

    // layer 1
    k_gemm<1><<<(NN + 127) / 128, 256, smem_gemm>>>(n_feat, W1);
    k_gather<1><<<(NN * 32 + 255) / 256, 256>>>(b1, (const int*)nullptr, (float*)nullptr);

    // layer 2 (+ fused sum-pool into d_out embedding)
    k_gemm<2><<<(NN + 127) / 128, 256, smem_gemm>>>((const float*)nullptr, W2);
    k_zero_out<<<(NG * FD + 255) / 256, 256>>>(out);
    k_gather<2><<<(NN * 32 + 255) / 256, 256>>>(b2, gids, out);

    // head
    k_bn<<<1, 128>>>(out, gamma, beta);
    k_fc1<<<NG / 8, 256, smem_fc1>>>(out, fc1w, fc1b);
    k_fc2ls<<<1, 1024>>>(fc2w, fc2b, out + NG * FD);
}